// round 6
// baseline (speedup 1.0000x reference)
#include <cuda_runtime.h>

// TempoStateRNNCell: c_t = a_t * c_{t-1} + b_t along time (T=2048).
// inputs: (16, 2048, 4096) fp32, [:, :, :2048]=a, [:, :, 2048:]=b
// output: (16, 2048, 2048) fp32.
//
// Time split into S=8 independent chunks per sequence. Each chunk does a
// 64-step unstored warm-up to rebuild the carry (prod(a) decays ~e^{-k},
// 64 steps -> ~1e-7 rel), then scans+stores its 256 steps. 262144 threads
// (~55 warps/SM) keep enough loads in flight to saturate HBM.
// Traffic: 768 MB floor + ~117 MB warm-up (partly L2-absorbed).

#define TSC_UNITS 2048
#define TSC_T     2048
#define TSC_BATCH 16
#define TSC_ROW   (2 * TSC_UNITS)
#define S_CHUNKS  8
#define CHUNK     (TSC_T / S_CHUNKS)   // 256
#define OV        64                   // warm-up steps
#define U         8                    // tile depth (double-buffered)

__global__ void __launch_bounds__(128)
tempo_scan_kernel(const float* __restrict__ in, float* __restrict__ out)
{
    const int gid   = blockIdx.x * blockDim.x + threadIdx.x;  // 0..262143
    const int unit  = gid & (TSC_UNITS - 1);
    const int chunk = (gid >> 11) & (S_CHUNKS - 1);
    const int batch = gid >> 14;

    const float* __restrict__ pa = in  + (size_t)batch * TSC_T * TSC_ROW + unit;
    const float* __restrict__ pb = pa + TSC_UNITS;
    float*       __restrict__ po = out + (size_t)batch * TSC_T * TSC_UNITS + unit;

    const int t0        = chunk * CHUNK;
    const int warmTiles = (chunk == 0) ? 0 : (OV / U);   // 0 or 8 (even!)
    const int tstart    = t0 - warmTiles * U;

    float A[2][U], B[2][U];

    // Prime buffer 0 at tstart
    #pragma unroll
    for (int i = 0; i < U; ++i) {
        A[0][i] = __ldcs(pa + (size_t)(tstart + i) * TSC_ROW);
        B[0][i] = __ldcs(pb + (size_t)(tstart + i) * TSC_ROW);
    }

    float c = 0.0f;
    size_t tnext = (size_t)tstart + U;   // next tile to prefetch

    // Warm-up: rebuild carry, no stores. warmTiles even -> stored loop
    // starts on buffer 0, all buffer indices stay compile-time.
    #pragma unroll 2
    for (int w = 0; w < warmTiles; ++w) {
        const int cur = w & 1, nxt = cur ^ 1;
        #pragma unroll
        for (int i = 0; i < U; ++i) {   // a stored tile always follows
            A[nxt][i] = __ldcs(pa + (tnext + i) * TSC_ROW);
            B[nxt][i] = __ldcs(pb + (tnext + i) * TSC_ROW);
        }
        #pragma unroll
        for (int i = 0; i < U; ++i)
            c = fmaf(A[cur][i], c, B[cur][i]);
        tnext += U;
    }

    // Stored region: [t0, t0 + CHUNK)
    const int NT = CHUNK / U;   // 32
    size_t ts = (size_t)t0;
    #pragma unroll 2
    for (int tile = 0; tile < NT; ++tile) {
        const int cur = tile & 1, nxt = cur ^ 1;
        if (tile + 1 < NT) {
            #pragma unroll
            for (int i = 0; i < U; ++i) {
                A[nxt][i] = __ldcs(pa + (tnext + i) * TSC_ROW);
                B[nxt][i] = __ldcs(pb + (tnext + i) * TSC_ROW);
            }
        }
        #pragma unroll
        for (int i = 0; i < U; ++i) {
            c = fmaf(A[cur][i], c, B[cur][i]);
            __stcs(po + (ts + i) * TSC_UNITS, c);
        }
        tnext += U;
        ts += U;
    }
}

extern "C" void kernel_launch(void* const* d_in, const int* in_sizes, int n_in,
                              void* d_out, int out_size)
{
    const float* in  = (const float*)d_in[0];
    float*       out = (float*)d_out;

    const int total_threads = TSC_BATCH * TSC_UNITS * S_CHUNKS;  // 262144
    const int block = 128;
    const int grid  = total_threads / block;                     // 2048

    tempo_scan_kernel<<<grid, block>>>(in, out);
}

// round 8
// speedup vs baseline: 1.1094x; 1.1094x over previous
#include <cuda_runtime.h>

// TempoStateRNNCell: c_t = a_t * c_{t-1} + b_t along time (T=2048).
// inputs: (16, 2048, 4096) fp32, [:, :, :2048]=a, [:, :, 2048:]=b
// output: (16, 2048, 2048) fp32. Traffic floor 768 MB -> HBM-bound.
//
// cp.async SMEM pipeline: 12-stage ring (96 KB/CTA), ~10 stages (~80 KB)
// permanently in flight per CTA -> ~20 MB chip-wide, decoupled from the
// register file and the serial fma chain. S=1: no warm-up traffic.
// 256 CTAs x 128 threads, one thread per (batch, unit) sequence.
//
// R7 bugfix: ALWAYS commit a (possibly empty) cp.async group per stage,
// so wait_group<NST-2> keeps pinning stage s even in the pipeline tail.

#define UNITS 2048
#define T_LEN 2048
#define BATCH 16
#define ROW   (2 * UNITS)          // 4096 floats per (batch, t) input row
#define BLK   128                  // threads = units per CTA
#define STEPS 8                    // timesteps per stage
#define NST   12                   // ring stages
#define STAGE_FLOATS (STEPS * BLK) // 1024 floats (4 KB) per matrix per stage
#define SMEM_BYTES (2 * NST * STAGE_FLOATS * 4)   // 96 KB

__device__ __forceinline__ void cp_async16(float* smem_dst, const float* gsrc) {
    unsigned saddr = (unsigned)__cvta_generic_to_shared(smem_dst);
    asm volatile("cp.async.cg.shared.global [%0], [%1], 16;\n"
                 :: "r"(saddr), "l"(gsrc));
}
__device__ __forceinline__ void cp_commit() {
    asm volatile("cp.async.commit_group;\n");
}
template <int N>
__device__ __forceinline__ void cp_wait() {
    asm volatile("cp.async.wait_group %0;\n" :: "n"(N));
}

__global__ void __launch_bounds__(BLK)
tempo_scan_kernel(const float* __restrict__ in, float* __restrict__ out)
{
    extern __shared__ float smem[];
    float* sa = smem;                        // [NST][STEPS][BLK]
    float* sb = smem + NST * STAGE_FLOATS;   // [NST][STEPS][BLK]

    const int tid   = threadIdx.x;
    const int batch = blockIdx.x >> 4;
    const int unit0 = (blockIdx.x & 15) * BLK;

    const float* __restrict__ gin = in + (size_t)batch * T_LEN * ROW + unit0;
    float* __restrict__ gout = out + (size_t)batch * T_LEN * UNITS + unit0 + tid;

    // Per-thread 16B-chunk mapping: 2 chunks per matrix per stage.
    // chunk c covers step (c>>5), floats [(c&31)*4, +4) of the 128-unit slab.
    const int c0 = tid,        c1 = tid + BLK;
    const int st0 = c0 >> 5,   col0 = (c0 & 31) * 4;
    const int st1 = c1 >> 5,   col1 = (c1 & 31) * 4;

    const int NSTG = T_LEN / STEPS;   // 256 stages

    // Issue stage s if it exists; ALWAYS commit a group (empty groups keep
    // the wait_group count aligned through the tail).
    auto issue = [&](int s) {
        if (s < NSTG) {
            const int slot = s % NST;
            const size_t tb = (size_t)s * STEPS;
            float* da = sa + slot * STAGE_FLOATS;
            float* db = sb + slot * STAGE_FLOATS;
            cp_async16(da + st0 * BLK + col0, gin + (tb + st0) * ROW + col0);
            cp_async16(da + st1 * BLK + col1, gin + (tb + st1) * ROW + col1);
            cp_async16(db + st0 * BLK + col0, gin + (tb + st0) * ROW + UNITS + col0);
            cp_async16(db + st1 * BLK + col1, gin + (tb + st1) * ROW + UNITS + col1);
        }
        cp_commit();
    };

    // Prime NST-1 stages (all real: NST-1 < NSTG)
    for (int s = 0; s < NST - 1; ++s) issue(s);

    float c = 0.0f;   // c_0 = fma(a_0, 0, b_0) = b_0

    for (int s = 0; s < NSTG; ++s) {
        cp_wait<NST - 2>();    // own groups for stage s retired
        __syncthreads();       // everyone's stage s visible; fences slot reuse

        // Keep the ring full: writes slot (s-1)%NST, which all threads
        // finished reading in iteration s-1 (ordered by the barrier above).
        issue(s + NST - 1);

        const int slot = s % NST;
        const float* da = sa + slot * STAGE_FLOATS + tid;
        const float* db = sb + slot * STAGE_FLOATS + tid;

        float ar[STEPS], br[STEPS];
        #pragma unroll
        for (int i = 0; i < STEPS; ++i) {
            ar[i] = da[i * BLK];
            br[i] = db[i * BLK];
        }

        const size_t tb = (size_t)s * STEPS;
        #pragma unroll
        for (int i = 0; i < STEPS; ++i) {
            c = fmaf(ar[i], c, br[i]);
            __stcs(gout + (tb + i) * UNITS, c);
        }
    }
}

extern "C" void kernel_launch(void* const* d_in, const int* in_sizes, int n_in,
                              void* d_out, int out_size)
{
    const float* in  = (const float*)d_in[0];
    float*       out = (float*)d_out;

    // Raise dynamic smem limit (attribute, not an allocation)
    cudaFuncSetAttribute(tempo_scan_kernel,
                         cudaFuncAttributeMaxDynamicSharedMemorySize, SMEM_BYTES);

    const int grid = BATCH * (UNITS / BLK);   // 256 CTAs
    tempo_scan_kernel<<<grid, BLK, SMEM_BYTES>>>(in, out);
}